// round 8
// baseline (speedup 1.0000x reference)
#include <cuda_runtime.h>
#include <cstdint>

typedef unsigned long long u64;

// ---------------------------------------------------------------------------
// BinaryNet forward, fully bitwise. Round 7: 2 img/thread ILP, warp-local
// ballot streams, conv2 via 6-bit row LUTs + byte-SIMD compares.
// ---------------------------------------------------------------------------

// Precomputed (pack kernel) tables in global, staged to smem by main kernel.
__device__ uint32_t g_lut1w[128];          // conv1 LUT: 512 bytes (9-bit patch -> 4 ch bits)
__device__ u64      g_T[384];              // conv2 row LUTs: [ (r*2+h)*64 + e ], byte o = popc6
__device__ uint32_t g_w3a[16], g_w3b[16], g_w3c[16];  // conv3 weights, pixel-major
__device__ uint32_t g_wfc1p[8];
__device__ uint32_t g_wfc2p;

__global__ void pack_weights_kernel(const float* __restrict__ w1,
                                    const float* __restrict__ w2,
                                    const float* __restrict__ w3,
                                    const float* __restrict__ wfc1,
                                    const float* __restrict__ wfc2) {
    __shared__ uint32_t w1p[4];
    __shared__ u64      w2p[8];
    const int t = threadIdx.x;

    if (t < 4) {
        uint32_t p = 0;
        for (int k = 0; k < 9; k++) p |= (uint32_t)(w1[t * 9 + k] > 0.0f) << k;
        w1p[t] = p;
    }
    if (t < 8) {
        u64 p = 0;
        for (int ic = 0; ic < 4; ic++)
            for (int k = 0; k < 9; k++)
                p |= (u64)(w2[(t * 4 + ic) * 9 + k] > 0.0f) << (k * 4 + ic);
        w2p[t] = p;
        uint32_t q = 0;
        for (int j = 0; j < 16; j++) q |= (uint32_t)(wfc1[t * 16 + j] > 0.0f) << j;
        g_wfc1p[t] = q;
    }
    if (t < 16) {   // conv3 weights, pixel-major: bit (pix*8 + ic)
        uint32_t a = 0, b = 0, c = 0;
        for (int ic = 0; ic < 8; ic++)
            for (int pix = 0; pix < 9; pix++) {
                uint32_t bit = (uint32_t)(w3[(t * 8 + ic) * 9 + pix] > 0.0f);
                if (pix < 4)      a |= bit << (pix * 8 + ic);
                else if (pix < 8) b |= bit << ((pix - 4) * 8 + ic);
                else              c |= bit << ic;
            }
        g_w3a[t] = a; g_w3b[t] = b; g_w3c[t] = c;
    }
    if (t == 0) {
        uint32_t p = 0;
        for (int j = 0; j < 8; j++) p |= (uint32_t)(wfc2[j] > 0.0f) << j;
        g_wfc2p = p;
    }
    __syncthreads();

    // conv1 LUT: entry e (9-bit patch) -> 4 bits of (popc(e^w1[ch]) <= 4)
    if (t < 512) {
        uint32_t e = (uint32_t)t;
        uint32_t nib =  (uint32_t)(__popc(e ^ w1p[0]) <= 4)
                     | ((uint32_t)(__popc(e ^ w1p[1]) <= 4) << 1)
                     | ((uint32_t)(__popc(e ^ w1p[2]) <= 4) << 2)
                     | ((uint32_t)(__popc(e ^ w1p[3]) <= 4) << 3);
        ((uint8_t*)g_lut1w)[t] = (uint8_t)nib;
    }
    // conv2 row LUTs: table tab = r*2+h (r=kernel row, h=6-bit half),
    // entry e: byte o = popc(e ^ ((w2p[o] >> (12r+6h)) & 63))
    if (t < 384) {
        int tab = t >> 6, e = t & 63;
        int sh  = (tab >> 1) * 12 + (tab & 1) * 6;
        u64 val = 0;
        for (int o = 0; o < 8; o++)
            val |= (u64)__popc((uint32_t)e ^ (uint32_t)((w2p[o] >> sh) & 63)) << (8 * o);
        g_T[t] = val;
    }
}

__global__ __launch_bounds__(128) void bnn_kernel(const float* __restrict__ x,
                                                  float* __restrict__ out,
                                                  int B) {
    // 128 threads, 2 images each -> 256 images/block. 4 warps, 64 img/warp.
    __shared__ uint32_t sbits[4][452];     // per-warp bitstream: 450 words + pad
    __shared__ uint32_t s_lut1w[128];
    __shared__ u64      sT[384];
    __shared__ uint32_t s_w3a[16], s_w3b[16], s_w3c[16];
    __shared__ uint32_t s_wfc1[8];
    __shared__ uint32_t s_wfc2;

    const int tid  = threadIdx.x;
    const int wrp  = tid >> 5;
    const int lane = tid & 31;

    // --- stage constants (visible after the __syncthreads below) ---
    s_lut1w[tid]   = g_lut1w[tid];
    sT[tid]        = g_T[tid];
    sT[tid + 128]  = g_T[tid + 128];
    sT[tid + 256]  = g_T[tid + 256];
    if (tid < 16) { s_w3a[tid] = g_w3a[tid]; s_w3b[tid] = g_w3b[tid]; s_w3c[tid] = g_w3c[tid]; }
    if (tid < 8)  s_wfc1[tid] = g_wfc1p[tid];
    if (tid == 0) s_wfc2 = g_wfc2p;

    // --- warp-local coalesced load + ballot binarization (64 images/warp) ---
    const int warpBase = blockIdx.x * (256 * 225) + wrp * (64 * 225);
    const int total    = B * 225;
    uint32_t* wb = sbits[wrp];
    if (warpBase + 450 * 32 <= total) {
        #pragma unroll 15
        for (int k = 0; k < 450; k++) {
            float v = __ldg(x + warpBase + k * 32 + lane);
            uint32_t b = __ballot_sync(0xFFFFFFFFu, v > 0.0f);
            if (lane == 0) wb[k] = b;
        }
    } else {
        for (int k = 0; k < 450; k++) {
            int idx = warpBase + k * 32 + lane;
            float v = (idx < total) ? __ldg(x + idx) : 0.0f;
            uint32_t b = __ballot_sync(0xFFFFFFFFu, v > 0.0f);
            if (lane == 0) wb[k] = b;
        }
    }
    __syncthreads();

    const uint8_t* lut1 = (const uint8_t*)s_lut1w;
    int res[2];

    #pragma unroll
    for (int half = 0; half < 2; half++) {
        const int imgLocal = lane + 32 * half;
        const int base     = imgLocal * 225;

        // --- extract 15 rows of 15 bits ---
        uint32_t rows[15];
        #pragma unroll
        for (int r = 0; r < 15; r++) {
            int off = base + r * 15;
            rows[r] = __funnelshift_r(wb[off >> 5], wb[(off >> 5) + 1], off & 31) & 0x7FFFu;
        }

        // --- conv1: 7x7, 4 channels, nibble-packed rows ---
        uint32_t q[7];
        #pragma unroll
        for (int orow = 0; orow < 7; orow++) {
            uint32_t r0 = rows[2 * orow], r1 = rows[2 * orow + 1], r2 = rows[2 * orow + 2];
            uint32_t acc = 0;
            #pragma unroll
            for (int oc = 0; oc < 7; oc++) {
                uint32_t patch = ((r0 >> (2 * oc)) & 7u)
                               | (((r1 >> (2 * oc)) & 7u) << 3)
                               | (((r2 >> (2 * oc)) & 7u) << 6);
                acc |= (uint32_t)lut1[patch] << (4 * oc);
            }
            q[orow] = acc;
        }

        // --- conv2: 3x3, 8 channels, ternary; 6-bit row LUTs + byte-SIMD ---
        // layout: bit (pix*8 + o); pix 0..3 -> v2a, 4..7 -> v2b, 8 -> v2c
        uint32_t v2a = 0, v2b = 0, v2c = 0, m2a = 0, m2b = 0, m2c = 0;
        #pragma unroll
        for (int R = 0; R < 3; R++) {
            uint32_t q0 = q[2 * R], q1 = q[2 * R + 1], q2 = q[2 * R + 2];
            #pragma unroll
            for (int C = 0; C < 3; C++) {
                uint32_t r0 = (q0 >> (8 * C)) & 0xFFFu;
                uint32_t r1 = (q1 >> (8 * C)) & 0xFFFu;
                uint32_t r2 = (q2 >> (8 * C)) & 0xFFFu;
                u64 d8 = sT[r0 & 63] + sT[64 + (r0 >> 6)]
                       + sT[128 + (r1 & 63)] + sT[192 + (r1 >> 6)]
                       + sT[256 + (r2 & 63)] + sT[320 + (r2 >> 6)];
                uint32_t dlo = (uint32_t)d8, dhi = (uint32_t)(d8 >> 32);
                // per-byte d in [0,36]: bit7(d+110) <=> d>=18 ; bit7(d+109) <=> d>=19
                uint32_t a18l = dlo + 0x6E6E6E6Eu, a18h = dhi + 0x6E6E6E6Eu;
                uint32_t a19l = dlo + 0x6D6D6D6Du, a19h = dhi + 0x6D6D6D6Du;
                uint32_t vl = (~a18l) & 0x80808080u;            // d<18  (sum>0)
                uint32_t vh = (~a18h) & 0x80808080u;
                uint32_t ml = ((~a18l) | a19l) & 0x80808080u;   // d!=18 (sum!=0)
                uint32_t mh = ((~a18h) | a19h) & 0x80808080u;
                uint32_t vbt = ((vl * 0x00204081u) >> 28) | (((vh * 0x00204081u) >> 28) << 4);
                uint32_t mbt = ((ml * 0x00204081u) >> 28) | (((mh * 0x00204081u) >> 28) << 4);
                const int pix = R * 3 + C;
                if (pix < 4)      { v2a |= vbt << (8 * pix);       m2a |= mbt << (8 * pix); }
                else if (pix < 8) { v2b |= vbt << (8 * (pix - 4)); m2b |= mbt << (8 * (pix - 4)); }
                else              { v2c = vbt;                     m2c = mbt; }
            }
        }

        // --- conv3: 16 channels, ternary ---
        const int mc2 = __popc(m2a) + __popc(m2b) + __popc(m2c);
        uint32_t v3 = 0, m3 = 0;
        #pragma unroll
        for (int o = 0; o < 16; o++) {
            int d = __popc(m2a & (v2a ^ s_w3a[o]))
                  + __popc(m2b & (v2b ^ s_w3b[o]))
                  + __popc(m2c & (v2c ^ s_w3c[o]));
            int s = mc2 - 2 * d;
            v3 |= (uint32_t)(s > 0)  << o;
            m3 |= (uint32_t)(s != 0) << o;
        }

        // --- fc1: 16 -> 8, ternary ---
        const int mc3 = __popc(m3);
        uint32_t v4 = 0, m4 = 0;
        #pragma unroll
        for (int o = 0; o < 8; o++) {
            int d = __popc(m3 & (v3 ^ s_wfc1[o]));
            int s = mc3 - 2 * d;
            v4 |= (uint32_t)(s > 0)  << o;
            m4 |= (uint32_t)(s != 0) << o;
        }

        // --- fc2: 8 -> 1, integer output ---
        int d5 = __popc(m4 & (v4 ^ s_wfc2));
        res[half] = __popc(m4) - 2 * d5;
    }

    const int img0 = blockIdx.x * 256 + wrp * 64 + lane;
    if (img0 < B)      out[img0]      = (float)res[0];
    if (img0 + 32 < B) out[img0 + 32] = (float)res[1];
}

extern "C" void kernel_launch(void* const* d_in, const int* in_sizes, int n_in,
                              void* d_out, int out_size) {
    const float* x    = (const float*)d_in[0];
    const float* w1   = (const float*)d_in[1];
    const float* w2   = (const float*)d_in[2];
    const float* w3   = (const float*)d_in[3];
    const float* wfc1 = (const float*)d_in[4];
    const float* wfc2 = (const float*)d_in[5];
    float* out = (float*)d_out;

    int B = in_sizes[0] / 225;                 // x is [B,1,15,15]
    pack_weights_kernel<<<1, 512>>>(w1, w2, w3, wfc1, wfc2);
    int blocks = (B + 255) / 256;              // 256 images per block
    bnn_kernel<<<blocks, 128>>>(x, out, B);
}

// round 9
// speedup vs baseline: 1.3916x; 1.3916x over previous
#include <cuda_runtime.h>
#include <cstdint>

typedef unsigned long long u64;

// ---------------------------------------------------------------------------
// BinaryNet forward, fully bitwise. R9: 1 img/thread (occupancy), 1024 blocks
// (load balance), warp-local bitstream (no block barrier between load/compute),
// conv2 via 6-bit row LUTs + byte-SIMD compares (instruction savings from R7).
// ---------------------------------------------------------------------------

__device__ uint32_t g_lut1w[128];          // conv1 LUT: 512 bytes (9-bit patch -> 4 ch bits)
__device__ u64      g_T[384];              // conv2 row LUTs: [(r*2+h)*64 + e], byte o = popc6
__device__ uint32_t g_w3a[16], g_w3b[16], g_w3c[16];  // conv3 weights, pixel-major
__device__ uint32_t g_wfc1p[8];
__device__ uint32_t g_wfc2p;

__global__ void pack_weights_kernel(const float* __restrict__ w1,
                                    const float* __restrict__ w2,
                                    const float* __restrict__ w3,
                                    const float* __restrict__ wfc1,
                                    const float* __restrict__ wfc2) {
    __shared__ uint32_t w1p[4];
    __shared__ u64      w2p[8];
    const int t = threadIdx.x;

    if (t < 4) {
        uint32_t p = 0;
        for (int k = 0; k < 9; k++) p |= (uint32_t)(w1[t * 9 + k] > 0.0f) << k;
        w1p[t] = p;
    }
    if (t < 8) {
        u64 p = 0;
        for (int ic = 0; ic < 4; ic++)
            for (int k = 0; k < 9; k++)
                p |= (u64)(w2[(t * 4 + ic) * 9 + k] > 0.0f) << (k * 4 + ic);
        w2p[t] = p;
        uint32_t q = 0;
        for (int j = 0; j < 16; j++) q |= (uint32_t)(wfc1[t * 16 + j] > 0.0f) << j;
        g_wfc1p[t] = q;
    }
    if (t < 16) {   // conv3 weights, pixel-major: bit (pix*8 + ic)
        uint32_t a = 0, b = 0, c = 0;
        for (int ic = 0; ic < 8; ic++)
            for (int pix = 0; pix < 9; pix++) {
                uint32_t bit = (uint32_t)(w3[(t * 8 + ic) * 9 + pix] > 0.0f);
                if (pix < 4)      a |= bit << (pix * 8 + ic);
                else if (pix < 8) b |= bit << ((pix - 4) * 8 + ic);
                else              c |= bit << ic;
            }
        g_w3a[t] = a; g_w3b[t] = b; g_w3c[t] = c;
    }
    if (t == 0) {
        uint32_t p = 0;
        for (int j = 0; j < 8; j++) p |= (uint32_t)(wfc2[j] > 0.0f) << j;
        g_wfc2p = p;
    }
    __syncthreads();

    // conv1 LUT: entry e (9-bit patch) -> 4 bits of (popc(e^w1[ch]) <= 4)
    if (t < 512) {
        uint32_t e = (uint32_t)t;
        uint32_t nib =  (uint32_t)(__popc(e ^ w1p[0]) <= 4)
                     | ((uint32_t)(__popc(e ^ w1p[1]) <= 4) << 1)
                     | ((uint32_t)(__popc(e ^ w1p[2]) <= 4) << 2)
                     | ((uint32_t)(__popc(e ^ w1p[3]) <= 4) << 3);
        ((uint8_t*)g_lut1w)[t] = (uint8_t)nib;
    }
    // conv2 row LUTs: table tab = r*2+h (r=kernel row, h=6-bit half),
    // entry e: byte o = popc(e ^ ((w2p[o] >> (12r+6h)) & 63))
    if (t < 384) {
        int tab = t >> 6, e = t & 63;
        int sh  = (tab >> 1) * 12 + (tab & 1) * 6;
        u64 val = 0;
        for (int o = 0; o < 8; o++)
            val |= (u64)__popc((uint32_t)e ^ (uint32_t)((w2p[o] >> sh) & 63)) << (8 * o);
        g_T[t] = val;
    }
}

__global__ __launch_bounds__(128) void bnn_kernel(const float* __restrict__ x,
                                                  float* __restrict__ out,
                                                  int B) {
    // 128 threads, 1 image each. 4 warps; each warp owns 32 images and a
    // warp-local bitstream of 32*225 bits = 225 words.
    __shared__ uint32_t sbits[4][226];     // 225 words + 1 pad for funnelshift
    __shared__ uint32_t s_lut1w[128];
    __shared__ u64      sT[384];
    __shared__ uint32_t s_w3a[16], s_w3b[16], s_w3c[16];
    __shared__ uint32_t s_wfc1[8];
    __shared__ uint32_t s_wfc2;

    const int tid  = threadIdx.x;
    const int wrp  = tid >> 5;
    const int lane = tid & 31;

    // --- stage constants ---
    s_lut1w[tid]  = g_lut1w[tid];
    sT[tid]       = g_T[tid];
    sT[tid + 128] = g_T[tid + 128];
    sT[tid + 256] = g_T[tid + 256];
    if (tid < 16) { s_w3a[tid] = g_w3a[tid]; s_w3b[tid] = g_w3b[tid]; s_w3c[tid] = g_w3c[tid]; }
    if (tid < 8)  s_wfc1[tid] = g_wfc1p[tid];
    if (tid == 0) s_wfc2 = g_wfc2p;
    __syncthreads();

    // --- warp-local coalesced load + ballot binarization (32 images/warp) ---
    const int warpBase = blockIdx.x * (128 * 225) + wrp * (32 * 225);
    const int total    = B * 225;
    uint32_t* wb = sbits[wrp];
    if (warpBase + 225 * 32 <= total) {
        #pragma unroll 15
        for (int k = 0; k < 225; k++) {
            float v = __ldg(x + warpBase + k * 32 + lane);
            uint32_t b = __ballot_sync(0xFFFFFFFFu, v > 0.0f);
            if (lane == 0) wb[k] = b;
        }
    } else {
        for (int k = 0; k < 225; k++) {
            int idx = warpBase + k * 32 + lane;
            float v = (idx < total) ? __ldg(x + idx) : 0.0f;
            uint32_t b = __ballot_sync(0xFFFFFFFFu, v > 0.0f);
            if (lane == 0) wb[k] = b;
        }
    }
    __syncwarp();   // lane 0's STS visible to the whole warp

    const uint8_t* lut1 = (const uint8_t*)s_lut1w;
    const int base = lane * 225;

    // --- extract 15 rows of 15 bits for this thread's image ---
    uint32_t rows[15];
    #pragma unroll
    for (int r = 0; r < 15; r++) {
        int off = base + r * 15;
        rows[r] = __funnelshift_r(wb[off >> 5], wb[(off >> 5) + 1], off & 31) & 0x7FFFu;
    }

    // --- conv1: 7x7, 4 channels, nibble-packed rows ---
    uint32_t q[7];
    #pragma unroll
    for (int orow = 0; orow < 7; orow++) {
        uint32_t r0 = rows[2 * orow], r1 = rows[2 * orow + 1], r2 = rows[2 * orow + 2];
        uint32_t acc = 0;
        #pragma unroll
        for (int oc = 0; oc < 7; oc++) {
            uint32_t patch = ((r0 >> (2 * oc)) & 7u)
                           | (((r1 >> (2 * oc)) & 7u) << 3)
                           | (((r2 >> (2 * oc)) & 7u) << 6);
            acc |= (uint32_t)lut1[patch] << (4 * oc);
        }
        q[orow] = acc;
    }

    // --- conv2: 3x3, 8 channels, ternary; 6-bit row LUTs + byte-SIMD ---
    // layout: bit (pix*8 + o); pix 0..3 -> v2a, 4..7 -> v2b, 8 -> v2c
    uint32_t v2a = 0, v2b = 0, v2c = 0, m2a = 0, m2b = 0, m2c = 0;
    #pragma unroll
    for (int R = 0; R < 3; R++) {
        uint32_t q0 = q[2 * R], q1 = q[2 * R + 1], q2 = q[2 * R + 2];
        #pragma unroll
        for (int C = 0; C < 3; C++) {
            uint32_t r0 = (q0 >> (8 * C)) & 0xFFFu;
            uint32_t r1 = (q1 >> (8 * C)) & 0xFFFu;
            uint32_t r2 = (q2 >> (8 * C)) & 0xFFFu;
            u64 d8 = sT[r0 & 63] + sT[64 + (r0 >> 6)]
                   + sT[128 + (r1 & 63)] + sT[192 + (r1 >> 6)]
                   + sT[256 + (r2 & 63)] + sT[320 + (r2 >> 6)];
            uint32_t dlo = (uint32_t)d8, dhi = (uint32_t)(d8 >> 32);
            // per-byte d in [0,36]: bit7(d+110) <=> d>=18 ; bit7(d+109) <=> d>=19
            uint32_t a18l = dlo + 0x6E6E6E6Eu, a18h = dhi + 0x6E6E6E6Eu;
            uint32_t a19l = dlo + 0x6D6D6D6Du, a19h = dhi + 0x6D6D6D6Du;
            uint32_t vl = (~a18l) & 0x80808080u;            // d<18  (sum>0)
            uint32_t vh = (~a18h) & 0x80808080u;
            uint32_t ml = ((~a18l) | a19l) & 0x80808080u;   // d!=18 (sum!=0)
            uint32_t mh = ((~a18h) | a19h) & 0x80808080u;
            uint32_t vbt = ((vl * 0x00204081u) >> 28) | (((vh * 0x00204081u) >> 28) << 4);
            uint32_t mbt = ((ml * 0x00204081u) >> 28) | (((mh * 0x00204081u) >> 28) << 4);
            const int pix = R * 3 + C;
            if (pix < 4)      { v2a |= vbt << (8 * pix);       m2a |= mbt << (8 * pix); }
            else if (pix < 8) { v2b |= vbt << (8 * (pix - 4)); m2b |= mbt << (8 * (pix - 4)); }
            else              { v2c = vbt;                     m2c = mbt; }
        }
    }

    // --- conv3: 16 channels, ternary ---
    const int mc2 = __popc(m2a) + __popc(m2b) + __popc(m2c);
    uint32_t v3 = 0, m3 = 0;
    #pragma unroll
    for (int o = 0; o < 16; o++) {
        int d = __popc(m2a & (v2a ^ s_w3a[o]))
              + __popc(m2b & (v2b ^ s_w3b[o]))
              + __popc(m2c & (v2c ^ s_w3c[o]));
        int s = mc2 - 2 * d;
        v3 |= (uint32_t)(s > 0)  << o;
        m3 |= (uint32_t)(s != 0) << o;
    }

    // --- fc1: 16 -> 8, ternary ---
    const int mc3 = __popc(m3);
    uint32_t v4 = 0, m4 = 0;
    #pragma unroll
    for (int o = 0; o < 8; o++) {
        int d = __popc(m3 & (v3 ^ s_wfc1[o]));
        int s = mc3 - 2 * d;
        v4 |= (uint32_t)(s > 0)  << o;
        m4 |= (uint32_t)(s != 0) << o;
    }

    // --- fc2: 8 -> 1, integer output ---
    int d5 = __popc(m4 & (v4 ^ s_wfc2));
    int res = __popc(m4) - 2 * d5;

    const int img = blockIdx.x * 128 + wrp * 32 + lane;
    if (img < B) out[img] = (float)res;
}

extern "C" void kernel_launch(void* const* d_in, const int* in_sizes, int n_in,
                              void* d_out, int out_size) {
    const float* x    = (const float*)d_in[0];
    const float* w1   = (const float*)d_in[1];
    const float* w2   = (const float*)d_in[2];
    const float* w3   = (const float*)d_in[3];
    const float* wfc1 = (const float*)d_in[4];
    const float* wfc2 = (const float*)d_in[5];
    float* out = (float*)d_out;

    int B = in_sizes[0] / 225;                 // x is [B,1,15,15]
    pack_weights_kernel<<<1, 512>>>(w1, w2, w3, wfc1, wfc2);
    int blocks = (B + 127) / 128;              // 128 images per block
    bnn_kernel<<<blocks, 128>>>(x, out, B);
}